// round 16
// baseline (speedup 1.0000x reference)
#include <cuda_runtime.h>
#include <cuda_fp16.h>
#include <cstdint>
#include <cfloat>

#define BB 2048
#define MM 65536
#define DD 32
#define CTA_B 128
#define CTA_M 128
#define MITER 4
#define CTA_MSPAN (CTA_M * MITER)    // 512
#define NCHB (MM / CTA_MSPAN)        // 128 (grid.x)
#define NBT  (BB / CTA_B)            // 16 (grid.y)
#define NCAND 1024                   // per b: 128 cta * 2 warp_m * 4 tg
#define THREADS 256
#define ROWB 80                      // smem row stride bytes (odd*16 -> LDSM conflict-free)
#define DELTA 0.25f                  // rescore band below approx max (>> 2*fp16 dot err)

typedef unsigned int u32;

// ---- global scratch (allocation-free) ----
__device__ __align__(16) __half g_wh[MM * DD];    // fp16 w
__device__ __align__(16) __half g_xh[BB * DD];    // fp16 x
__device__ float g_wn[MM];                        // exact -||w||^2/2
__device__ float g_cv[BB * NCAND];                // per-(b,group) max approx score
__device__ int   g_it[BB * NCAND];                // winning iteration of that group

__device__ __forceinline__ u32 smem_u32(const void* p) {
    u32 a;
    asm("{ .reg .u64 t; cvta.to.shared.u64 t, %1; cvt.u32.u64 %0, t; }"
        : "=r"(a) : "l"(p));
    return a;
}

__device__ __forceinline__ u32 h2_bits(__half2 h) {
    return *reinterpret_cast<u32*>(&h);
}

#define LDSM4(r, addr) \
    asm volatile("ldmatrix.sync.aligned.m8n8.x4.shared.b16 {%0,%1,%2,%3}, [%4];" \
        : "=r"((r)[0]), "=r"((r)[1]), "=r"((r)[2]), "=r"((r)[3]) : "r"(addr))

#define MMA16816(c, a, b0v, b1v) \
    asm volatile("mma.sync.aligned.m16n8k16.row.col.f32.f16.f16.f32 " \
        "{%0,%1,%2,%3}, {%4,%5,%6,%7}, {%8,%9}, {%0,%1,%2,%3};" \
        : "+f"((c)[0]), "+f"((c)[1]), "+f"((c)[2]), "+f"((c)[3]) \
        : "r"((a)[0]), "r"((a)[1]), "r"((a)[2]), "r"((a)[3]), "r"(b0v), "r"(b1v))

#define CPA16(d, s)  asm volatile("cp.async.cg.shared.global [%0], [%1], 16;" :: "r"(d), "l"(s))
#define CPA4(d, s)   asm volatile("cp.async.ca.shared.global [%0], [%1], 4;"  :: "r"(d), "l"(s))
#define CPA_COMMIT() asm volatile("cp.async.commit_group;" ::: "memory")
#define CPA_WAIT(n)  asm volatile("cp.async.wait_group %0;" :: "n"(n) : "memory")

// ---------------- Prepass: fp32 -> fp16 + exact -||w||^2/2 (4 thr/row, MLP 2) ----------------
__global__ void conv_h(const float* __restrict__ x, const float* __restrict__ w)
{
    const int gt = blockIdx.x * blockDim.x + threadIdx.x;
    const int W_THREADS = MM * 4;
    const bool is_w = gt < W_THREADS;
    const int  t    = is_w ? gt : gt - W_THREADS;
    const int  row  = t >> 2;
    const int  q    = t & 3;     // owns float4 pair (2q, 2q+1)
    if (!is_w && row >= BB) return;

    const float4* src = reinterpret_cast<const float4*>(is_w ? w : x) + row * 8;
    const float4 a = src[2 * q];
    const float4 c = src[2 * q + 1];
    uint4 packed;
    packed.x = h2_bits(__halves2half2(__float2half_rn(a.x), __float2half_rn(a.y)));
    packed.y = h2_bits(__halves2half2(__float2half_rn(a.z), __float2half_rn(a.w)));
    packed.z = h2_bits(__halves2half2(__float2half_rn(c.x), __float2half_rn(c.y)));
    packed.w = h2_bits(__halves2half2(__float2half_rn(c.z), __float2half_rn(c.w)));
    reinterpret_cast<uint4*>((is_w ? g_wh : g_xh) + row * DD)[q] = packed;
    if (is_w) {
        float n = a.x * a.x + a.y * a.y + a.z * a.z + a.w * a.w
                + c.x * c.x + c.y * c.y + c.z * c.z + c.w * c.w;
        n += __shfl_xor_sync(0xffffffffu, n, 1);
        n += __shfl_xor_sync(0xffffffffu, n, 2);
        if (q == 0) g_wn[row] = -0.5f * n;
    }
}

// pads: keep ncu's capture window on som_mma (our launch #3)
__global__ void pad_a() {}
__global__ void pad_b() {}

// ---------------- Main: fp16 GEMM (32b x 64m warp tile), value+iter epilogue ----------------
__global__ __launch_bounds__(THREADS, 2)
void som_mma()
{
    __shared__ __align__(16) char xs[CTA_B * ROWB];
    __shared__ __align__(16) char ws[2][CTA_M * ROWB];
    __shared__ __align__(16) float wn_s[2][CTA_M];

    const int tid  = threadIdx.x;
    const int wid  = tid >> 5;
    const int lane = tid & 31;
    const int b0   = blockIdx.y * CTA_B;
    const int mc0  = blockIdx.x * CTA_MSPAN;

    const u32 xs_b    = smem_u32(xs);
    const u32 ws_b[2] = { smem_u32(ws[0]), smem_u32(ws[1]) };
    const u32 wn_b[2] = { smem_u32(wn_s[0]), smem_u32(wn_s[1]) };

#pragma unroll
    for (int j = 0; j < 2; j++) {
        const int i = tid + j * 256;
        const int r = i >> 2, q = i & 3;
        CPA16(xs_b + r * ROWB + q * 16, &g_xh[(size_t)(b0 + r) * DD + q * 8]);
        CPA16(ws_b[0] + r * ROWB + q * 16, &g_wh[(size_t)(mc0 + r) * DD + q * 8]);
    }
    if (tid < 128) CPA4(wn_b[0] + tid * 4, &g_wn[mc0 + tid]);
    CPA_COMMIT();

    // warp tiling: 4 b-warps x 2 m-warps; warp tile 32b x 64m
    const int warp_b = wid >> 1;
    const int warp_m = wid & 1;
    const int a_row  = warp_b * 32 + (lane & 15);
    const int a_koff = (lane >> 4) * 8;
    const int b_row  = warp_m * 64 + (lane & 7) + ((lane >> 4) << 3);
    const int b_koff = ((lane >> 3) & 1) * 8;
    const int tg     = lane & 3;
    const int mbase  = warp_m * 64 + 2 * tg;

    // per-slot running max value + winning iteration (group = 16 m's)
    float vmax[4] = {-FLT_MAX, -FLT_MAX, -FLT_MAX, -FLT_MAX};
    int   vit[4]  = {0, 0, 0, 0};

    for (int it = 0; it < MITER; it++) {
        const int cur = it & 1;
        if (it + 1 < MITER) {
            const int nxt = (it + 1) & 1;
            const int m0  = mc0 + (it + 1) * CTA_M;
#pragma unroll
            for (int j = 0; j < 2; j++) {
                const int i = tid + j * 256;
                const int r = i >> 2, q = i & 3;
                CPA16(ws_b[nxt] + r * ROWB + q * 16, &g_wh[(size_t)(m0 + r) * DD + q * 8]);
            }
            if (tid < 128) CPA4(wn_b[nxt] + tid * 4, &g_wn[m0 + tid]);
            CPA_COMMIT();
            CPA_WAIT(1);
        } else {
            CPA_WAIT(0);
        }
        __syncthreads();

        float acc[2][8][4];
#pragma unroll
        for (int bf = 0; bf < 2; bf++)
#pragma unroll
            for (int jj = 0; jj < 8; jj++)
#pragma unroll
                for (int e = 0; e < 4; e++) acc[bf][jj][e] = 0.f;

#pragma unroll
        for (int k2 = 0; k2 < 2; k2++) {
            const int k0 = k2 * 16;
            u32 af[2][4];
#pragma unroll
            for (int bf = 0; bf < 2; bf++)
                LDSM4(af[bf], xs_b + (u32)(a_row + bf * 16) * ROWB + (u32)(k0 + a_koff) * 2);
#pragma unroll
            for (int nbp = 0; nbp < 4; nbp++) {
                u32 bfr[4];
                LDSM4(bfr, ws_b[cur] + (u32)(b_row + nbp * 16) * ROWB + (u32)(k0 + b_koff) * 2);
#pragma unroll
                for (int bf = 0; bf < 2; bf++) {
                    MMA16816(acc[bf][2 * nbp],     af[bf], bfr[0], bfr[1]);
                    MMA16816(acc[bf][2 * nbp + 1], af[bf], bfr[2], bfr[3]);
                }
            }
        }

        // ---- epilogue: 16 FADD + FMNMX tree + predicated (vmax,vit) update ----
        const float* wnp = wn_s[cur];
        float wnr[16];
#pragma unroll
        for (int jj = 0; jj < 8; jj++) {
            wnr[2 * jj]     = wnp[mbase + 8 * jj];
            wnr[2 * jj + 1] = wnp[mbase + 8 * jj + 1];
        }
#pragma unroll
        for (int bf = 0; bf < 2; bf++) {
#pragma unroll
            for (int rh = 0; rh < 2; rh++) {
                const int s = bf * 2 + rh;
                float t8[8];
#pragma unroll
                for (int jj = 0; jj < 8; jj++)
                    t8[jj] = fmaxf(acc[bf][jj][rh * 2 + 0] + wnr[2 * jj],
                                   acc[bf][jj][rh * 2 + 1] + wnr[2 * jj + 1]);
                float t = fmaxf(fmaxf(fmaxf(t8[0], t8[1]), fmaxf(t8[2], t8[3])),
                                fmaxf(fmaxf(t8[4], t8[5]), fmaxf(t8[6], t8[7])));
                if (t > vmax[s]) { vmax[s] = t; vit[s] = it; }  // strict >: earliest it
            }
        }
        __syncthreads();
    }

    // store (value, iter) per (slot, tg): group = 16 m's
    const int cidx = (blockIdx.x * 2 + warp_m) * 4 + tg;
#pragma unroll
    for (int s = 0; s < 4; s++) {
        const int bf = s >> 1, rh = s & 1;
        const int bg = b0 + warp_b * 32 + bf * 16 + rh * 8 + (lane >> 2);
        g_cv[(size_t)bg * NCAND + cidx] = vmax[s];
        g_it[(size_t)bg * NCAND + cidx] = vit[s];
    }
}

// ---------------- Final: ballot qualifying groups, exact fp32 rescore of 16 m's ----------------
__global__ void som_pick(const float* __restrict__ x, const float* __restrict__ w,
                         const float* __restrict__ grid_flat, float* __restrict__ out)
{
    const int gtid = blockIdx.x * blockDim.x + threadIdx.x;
    const int b    = gtid >> 5;
    const int lane = gtid & 31;
    if (b >= BB) return;

    float cv[32];
    float amax = -FLT_MAX;
#pragma unroll
    for (int k = 0; k < 32; k++) {
        cv[k] = g_cv[(size_t)b * NCAND + (lane + k * 32)];
        amax = fmaxf(amax, cv[k]);
    }
#pragma unroll
    for (int off = 16; off > 0; off >>= 1)
        amax = fmaxf(amax, __shfl_xor_sync(0xffffffffu, amax, off));
    const float band = amax - DELTA;

    const float4* xr = reinterpret_cast<const float4*>(x + (size_t)b * DD);
    float4 xv[8];
#pragma unroll
    for (int q = 0; q < 8; q++) xv[q] = xr[q];

    float es = -FLT_MAX;
    int   ei = 0x7fffffff;

    // 16 lanes rescore the 16 m's of each qualifying group (g_it loaded lazily)
    for (int k = 0; k < 32; k++) {
        u32 mask = __ballot_sync(0xffffffffu, cv[k] >= band);
        while (mask) {
            const int src = __ffs(mask) - 1;
            mask &= mask - 1;
            const int c      = src + k * 32;
            const int itv    = g_it[(size_t)b * NCAND + c];  // broadcast load
            const int cta    = c >> 3;
            const int warp_m = (c >> 2) & 1;
            const int tgc    = c & 3;
            const int gb     = cta * CTA_MSPAN + itv * CTA_M + warp_m * 64 + 2 * tgc;
            if (lane < 16) {
                const int m = gb + 8 * (lane >> 1) + (lane & 1);
                const float4* wr = reinterpret_cast<const float4*>(w + (size_t)m * DD);
                float s = g_wn[m];
#pragma unroll
                for (int q = 0; q < 8; q++) {
                    float4 wv = wr[q];
                    s += xv[q].x * wv.x + xv[q].y * wv.y + xv[q].z * wv.z + xv[q].w * wv.w;
                }
                if (s > es || (s == es && m < ei)) { es = s; ei = m; }
            }
        }
    }

    // exact warp argmax with lowest-index tie-break
#pragma unroll
    for (int off = 16; off > 0; off >>= 1) {
        float s2 = __shfl_xor_sync(0xffffffffu, es, off);
        int   j2 = __shfl_xor_sync(0xffffffffu, ei, off);
        if (s2 > es || (s2 == es && j2 < ei)) { es = s2; ei = j2; }
    }
    if (lane == 0) {
        out[b * 2 + 0] = grid_flat[(size_t)ei * 2 + 0];
        out[b * 2 + 1] = grid_flat[(size_t)ei * 2 + 1];
    }
}

extern "C" void kernel_launch(void* const* d_in, const int* in_sizes, int n_in,
                              void* d_out, int out_size)
{
    const float* x = nullptr;
    const float* grid = nullptr;
    const float* w = nullptr;
    for (int i = 0; i < n_in; i++) {
        if      (in_sizes[i] == BB * DD) x    = (const float*)d_in[i];
        else if (in_sizes[i] == MM * 2)  grid = (const float*)d_in[i];
        else if (in_sizes[i] == MM * DD) w    = (const float*)d_in[i];
    }

    const int conv_threads = (MM + BB) * 4;
    conv_h<<<(conv_threads + 255) / 256, 256>>>(x, w);   // #0
    pad_a<<<1, 32>>>();                                  // #1
    pad_b<<<1, 32>>>();                                  // #2
    dim3 g(NCHB, NBT);
    som_mma<<<g, THREADS>>>();                           // #3 -> ncu target
    som_pick<<<(BB * 32 + 255) / 256, 256>>>(x, w, grid, (float*)d_out);  // #4
}

// round 17
// speedup vs baseline: 1.1372x; 1.1372x over previous
#include <cuda_runtime.h>
#include <cuda_fp16.h>
#include <cstdint>
#include <cfloat>

#define BB 2048
#define MM 65536
#define DD 32
#define CTA_B 128
#define CTA_M 128
#define MITER 8
#define CTA_MSPAN (CTA_M * MITER)    // 1024
#define NCHB (MM / CTA_MSPAN)        // 64 (grid.x)
#define NBT  (BB / CTA_B)            // 16 (grid.y)
#define NCAND 512                    // per b: 64 cta * 2 warp_m * 4 tg
#define THREADS 256
#define ROWB 80                      // smem row stride bytes (odd*16 -> LDSM conflict-free)
#define DELTA 0.25f                  // rescore band below approx max (>> 2*fp16 dot err)

typedef unsigned int u32;

// ---- global scratch (allocation-free) ----
__device__ __align__(16) __half g_wh[MM * DD];    // fp16 w
__device__ __align__(16) __half g_xh[BB * DD];    // fp16 x
__device__ float g_wn[MM];                        // exact -||w||^2/2
__device__ float g_cv[BB * NCAND];                // per-(b,group) max approx score
__device__ int   g_it[BB * NCAND];                // winning iteration of that group

__device__ __forceinline__ u32 smem_u32(const void* p) {
    u32 a;
    asm("{ .reg .u64 t; cvta.to.shared.u64 t, %1; cvt.u32.u64 %0, t; }"
        : "=r"(a) : "l"(p));
    return a;
}

__device__ __forceinline__ u32 h2_bits(__half2 h) {
    return *reinterpret_cast<u32*>(&h);
}

#define LDSM4(r, addr) \
    asm volatile("ldmatrix.sync.aligned.m8n8.x4.shared.b16 {%0,%1,%2,%3}, [%4];" \
        : "=r"((r)[0]), "=r"((r)[1]), "=r"((r)[2]), "=r"((r)[3]) : "r"(addr))

#define MMA16816(c, a, b0v, b1v) \
    asm volatile("mma.sync.aligned.m16n8k16.row.col.f32.f16.f16.f32 " \
        "{%0,%1,%2,%3}, {%4,%5,%6,%7}, {%8,%9}, {%0,%1,%2,%3};" \
        : "+f"((c)[0]), "+f"((c)[1]), "+f"((c)[2]), "+f"((c)[3]) \
        : "r"((a)[0]), "r"((a)[1]), "r"((a)[2]), "r"((a)[3]), "r"(b0v), "r"(b1v))

#define CPA16(d, s)  asm volatile("cp.async.cg.shared.global [%0], [%1], 16;" :: "r"(d), "l"(s))
#define CPA4(d, s)   asm volatile("cp.async.ca.shared.global [%0], [%1], 4;"  :: "r"(d), "l"(s))
#define CPA_COMMIT() asm volatile("cp.async.commit_group;" ::: "memory")
#define CPA_WAIT(n)  asm volatile("cp.async.wait_group %0;" :: "n"(n) : "memory")

// ---------------- Prepass: fp32 -> fp16 + exact -||w||^2/2 (4 thr/row, MLP 2) ----------------
__global__ void conv_h(const float* __restrict__ x, const float* __restrict__ w)
{
    const int gt = blockIdx.x * blockDim.x + threadIdx.x;
    const int W_THREADS = MM * 4;
    const bool is_w = gt < W_THREADS;
    const int  t    = is_w ? gt : gt - W_THREADS;
    const int  row  = t >> 2;
    const int  q    = t & 3;     // owns float4 pair (2q, 2q+1)
    if (!is_w && row >= BB) return;

    const float4* src = reinterpret_cast<const float4*>(is_w ? w : x) + row * 8;
    const float4 a = src[2 * q];
    const float4 c = src[2 * q + 1];
    uint4 packed;
    packed.x = h2_bits(__halves2half2(__float2half_rn(a.x), __float2half_rn(a.y)));
    packed.y = h2_bits(__halves2half2(__float2half_rn(a.z), __float2half_rn(a.w)));
    packed.z = h2_bits(__halves2half2(__float2half_rn(c.x), __float2half_rn(c.y)));
    packed.w = h2_bits(__halves2half2(__float2half_rn(c.z), __float2half_rn(c.w)));
    reinterpret_cast<uint4*>((is_w ? g_wh : g_xh) + row * DD)[q] = packed;
    if (is_w) {
        float n = a.x * a.x + a.y * a.y + a.z * a.z + a.w * a.w
                + c.x * c.x + c.y * c.y + c.z * c.z + c.w * c.w;
        n += __shfl_xor_sync(0xffffffffu, n, 1);
        n += __shfl_xor_sync(0xffffffffu, n, 2);
        if (q == 0) g_wn[row] = -0.5f * n;
    }
}

// ---------------- Main: fp16 GEMM (32b x 64m warp tile), value+iter epilogue ----------------
__global__ __launch_bounds__(THREADS, 2)
void som_mma()
{
    __shared__ __align__(16) char xs[CTA_B * ROWB];
    __shared__ __align__(16) char ws[2][CTA_M * ROWB];
    __shared__ __align__(16) float wn_s[2][CTA_M];

    const int tid  = threadIdx.x;
    const int wid  = tid >> 5;
    const int lane = tid & 31;
    const int b0   = blockIdx.y * CTA_B;
    const int mc0  = blockIdx.x * CTA_MSPAN;

    const u32 xs_b    = smem_u32(xs);
    const u32 ws_b[2] = { smem_u32(ws[0]), smem_u32(ws[1]) };
    const u32 wn_b[2] = { smem_u32(wn_s[0]), smem_u32(wn_s[1]) };

#pragma unroll
    for (int j = 0; j < 2; j++) {
        const int i = tid + j * 256;
        const int r = i >> 2, q = i & 3;
        CPA16(xs_b + r * ROWB + q * 16, &g_xh[(size_t)(b0 + r) * DD + q * 8]);
        CPA16(ws_b[0] + r * ROWB + q * 16, &g_wh[(size_t)(mc0 + r) * DD + q * 8]);
    }
    if (tid < 128) CPA4(wn_b[0] + tid * 4, &g_wn[mc0 + tid]);
    CPA_COMMIT();

    // warp tiling: 4 b-warps x 2 m-warps; warp tile 32b x 64m
    const int warp_b = wid >> 1;
    const int warp_m = wid & 1;
    const int a_row  = warp_b * 32 + (lane & 15);
    const int a_koff = (lane >> 4) * 8;
    const int b_row  = warp_m * 64 + (lane & 7) + ((lane >> 4) << 3);
    const int b_koff = ((lane >> 3) & 1) * 8;
    const int tg     = lane & 3;
    const int mbase  = warp_m * 64 + 2 * tg;

    // per-slot running max value + winning iteration (group = 16 m's)
    float vmax[4] = {-FLT_MAX, -FLT_MAX, -FLT_MAX, -FLT_MAX};
    int   vit[4]  = {0, 0, 0, 0};

    for (int it = 0; it < MITER; it++) {
        const int cur = it & 1;
        if (it + 1 < MITER) {
            const int nxt = (it + 1) & 1;
            const int m0  = mc0 + (it + 1) * CTA_M;
#pragma unroll
            for (int j = 0; j < 2; j++) {
                const int i = tid + j * 256;
                const int r = i >> 2, q = i & 3;
                CPA16(ws_b[nxt] + r * ROWB + q * 16, &g_wh[(size_t)(m0 + r) * DD + q * 8]);
            }
            if (tid < 128) CPA4(wn_b[nxt] + tid * 4, &g_wn[m0 + tid]);
            CPA_COMMIT();
            CPA_WAIT(1);
        } else {
            CPA_WAIT(0);
        }
        __syncthreads();

        float acc[2][8][4];
#pragma unroll
        for (int bf = 0; bf < 2; bf++)
#pragma unroll
            for (int jj = 0; jj < 8; jj++)
#pragma unroll
                for (int e = 0; e < 4; e++) acc[bf][jj][e] = 0.f;

#pragma unroll
        for (int k2 = 0; k2 < 2; k2++) {
            const int k0 = k2 * 16;
            u32 af[2][4];
#pragma unroll
            for (int bf = 0; bf < 2; bf++)
                LDSM4(af[bf], xs_b + (u32)(a_row + bf * 16) * ROWB + (u32)(k0 + a_koff) * 2);
#pragma unroll
            for (int nbp = 0; nbp < 4; nbp++) {
                u32 bfr[4];
                LDSM4(bfr, ws_b[cur] + (u32)(b_row + nbp * 16) * ROWB + (u32)(k0 + b_koff) * 2);
#pragma unroll
                for (int bf = 0; bf < 2; bf++) {
                    MMA16816(acc[bf][2 * nbp],     af[bf], bfr[0], bfr[1]);
                    MMA16816(acc[bf][2 * nbp + 1], af[bf], bfr[2], bfr[3]);
                }
            }
        }

        // ---- epilogue: 16 FADD + FMNMX tree + predicated (vmax,vit) update ----
        const float* wnp = wn_s[cur];
        float wnr[16];
#pragma unroll
        for (int jj = 0; jj < 8; jj++) {
            wnr[2 * jj]     = wnp[mbase + 8 * jj];
            wnr[2 * jj + 1] = wnp[mbase + 8 * jj + 1];
        }
#pragma unroll
        for (int bf = 0; bf < 2; bf++) {
#pragma unroll
            for (int rh = 0; rh < 2; rh++) {
                const int s = bf * 2 + rh;
                float t8[8];
#pragma unroll
                for (int jj = 0; jj < 8; jj++)
                    t8[jj] = fmaxf(acc[bf][jj][rh * 2 + 0] + wnr[2 * jj],
                                   acc[bf][jj][rh * 2 + 1] + wnr[2 * jj + 1]);
                float t = fmaxf(fmaxf(fmaxf(t8[0], t8[1]), fmaxf(t8[2], t8[3])),
                                fmaxf(fmaxf(t8[4], t8[5]), fmaxf(t8[6], t8[7])));
                if (t > vmax[s]) { vmax[s] = t; vit[s] = it; }  // strict >: earliest it
            }
        }
        __syncthreads();
    }

    // store (value, iter) per (slot, tg): group = 16 m's
    const int cidx = (blockIdx.x * 2 + warp_m) * 4 + tg;
#pragma unroll
    for (int s = 0; s < 4; s++) {
        const int bf = s >> 1, rh = s & 1;
        const int bg = b0 + warp_b * 32 + bf * 16 + rh * 8 + (lane >> 2);
        g_cv[(size_t)bg * NCAND + cidx] = vmax[s];
        g_it[(size_t)bg * NCAND + cidx] = vit[s];
    }
}

// ---------------- Final: ballot qualifying groups, exact fp32 rescore of 16 m's ----------------
__global__ void som_pick(const float* __restrict__ x, const float* __restrict__ w,
                         const float* __restrict__ grid_flat, float* __restrict__ out)
{
    const int gtid = blockIdx.x * blockDim.x + threadIdx.x;
    const int b    = gtid >> 5;
    const int lane = gtid & 31;
    if (b >= BB) return;

    float cv[16];
    float amax = -FLT_MAX;
#pragma unroll
    for (int k = 0; k < 16; k++) {
        cv[k] = g_cv[(size_t)b * NCAND + (lane + k * 32)];
        amax = fmaxf(amax, cv[k]);
    }
#pragma unroll
    for (int off = 16; off > 0; off >>= 1)
        amax = fmaxf(amax, __shfl_xor_sync(0xffffffffu, amax, off));
    const float band = amax - DELTA;

    const float4* xr = reinterpret_cast<const float4*>(x + (size_t)b * DD);
    float4 xv[8];
#pragma unroll
    for (int q = 0; q < 8; q++) xv[q] = xr[q];

    float es = -FLT_MAX;
    int   ei = 0x7fffffff;

    // 16 lanes rescore the 16 m's of each qualifying group (g_it loaded lazily)
    for (int k = 0; k < 16; k++) {
        u32 mask = __ballot_sync(0xffffffffu, cv[k] >= band);
        while (mask) {
            const int src = __ffs(mask) - 1;
            mask &= mask - 1;
            const int c      = src + k * 32;
            const int itv    = g_it[(size_t)b * NCAND + c];  // broadcast load
            const int cta    = c >> 3;
            const int warp_m = (c >> 2) & 1;
            const int tgc    = c & 3;
            const int gb     = cta * CTA_MSPAN + itv * CTA_M + warp_m * 64 + 2 * tgc;
            if (lane < 16) {
                const int m = gb + 8 * (lane >> 1) + (lane & 1);
                const float4* wr = reinterpret_cast<const float4*>(w + (size_t)m * DD);
                float s = g_wn[m];
#pragma unroll
                for (int q = 0; q < 8; q++) {
                    float4 wv = wr[q];
                    s += xv[q].x * wv.x + xv[q].y * wv.y + xv[q].z * wv.z + xv[q].w * wv.w;
                }
                if (s > es || (s == es && m < ei)) { es = s; ei = m; }
            }
        }
    }

    // exact warp argmax with lowest-index tie-break
#pragma unroll
    for (int off = 16; off > 0; off >>= 1) {
        float s2 = __shfl_xor_sync(0xffffffffu, es, off);
        int   j2 = __shfl_xor_sync(0xffffffffu, ei, off);
        if (s2 > es || (s2 == es && j2 < ei)) { es = s2; ei = j2; }
    }
    if (lane == 0) {
        out[b * 2 + 0] = grid_flat[(size_t)ei * 2 + 0];
        out[b * 2 + 1] = grid_flat[(size_t)ei * 2 + 1];
    }
}

extern "C" void kernel_launch(void* const* d_in, const int* in_sizes, int n_in,
                              void* d_out, int out_size)
{
    const float* x = nullptr;
    const float* grid = nullptr;
    const float* w = nullptr;
    for (int i = 0; i < n_in; i++) {
        if      (in_sizes[i] == BB * DD) x    = (const float*)d_in[i];
        else if (in_sizes[i] == MM * 2)  grid = (const float*)d_in[i];
        else if (in_sizes[i] == MM * DD) w    = (const float*)d_in[i];
    }

    const int conv_threads = (MM + BB) * 4;
    conv_h<<<(conv_threads + 255) / 256, 256>>>(x, w);
    dim3 g(NCHB, NBT);
    som_mma<<<g, THREADS>>>();
    som_pick<<<(BB * 32 + 255) / 256, 256>>>(x, w, grid, (float*)d_out);
}